// round 7
// baseline (speedup 1.0000x reference)
#include <cuda_runtime.h>
#include <cstdint>

#define NN 10000
#define EE 160000
#define EP 170000      // E + N self loops
#define DIN 4096
#define DH 256
#define HEADS 4
#define OUTC 228       // 128 + 100

// ---------------- scratch (static device globals; no allocs) ----------------
__device__ float g_hidden[NN * DH];        // 10.24 MB
__device__ float g_xl[NN * 512];           // 20.5 MB (max H*C = 512)
__device__ float g_xr[NN * 512];           // 20.5 MB
__device__ int   g_cnt[NN];
__device__ int   g_row[NN + 1];
__device__ int   g_cur[NN];
__device__ int   g_eids[EP];

// ---------------- CSR build ----------------
__global__ void k_zero_cnt() {
    int i = blockIdx.x * blockDim.x + threadIdx.x;
    if (i < NN) g_cnt[i] = 0;
}

__global__ void k_hist(const int* __restrict__ ei) {
    int e = blockIdx.x * blockDim.x + threadIdx.x;
    if (e >= EP) return;
    int dst = (e < EE) ? ei[EE + e] : (e - EE);
    atomicAdd(&g_cnt[dst], 1);
}

__global__ void k_scan() {
    __shared__ int sh[1024];
    __shared__ int s_off;
    int tid = threadIdx.x;
    if (tid == 0) s_off = 0;
    __syncthreads();
    for (int base = 0; base < NN; base += 1024) {
        int v = (base + tid < NN) ? g_cnt[base + tid] : 0;
        sh[tid] = v;
        __syncthreads();
        for (int d = 1; d < 1024; d <<= 1) {
            int t = (tid >= d) ? sh[tid - d] : 0;
            __syncthreads();
            sh[tid] += t;
            __syncthreads();
        }
        int incl = sh[tid];
        int tot  = sh[1023];
        int off  = s_off;
        __syncthreads();
        if (base + tid < NN) {
            int excl = off + incl - v;
            g_row[base + tid] = excl;
            g_cur[base + tid] = excl;
        }
        if (tid == 0) s_off = off + tot;
        __syncthreads();
    }
    if (tid == 0) g_row[NN] = s_off;
}

__global__ void k_scatter(const int* __restrict__ ei) {
    int e = blockIdx.x * blockDim.x + threadIdx.x;
    if (e >= EP) return;
    int dst = (e < EE) ? ei[EE + e] : (e - EE);
    int pos = atomicAdd(&g_cur[dst], 1);
    g_eids[pos] = e;
}

// =================== 3xTF32 tensor-core GEMM (legacy mma.sync — sm_100-safe) ===================
// C[M,N] = A[M,K] @ B[K,N] (+bias, +relu).  Requires K % 16 == 0, N % 4 == 0.
#define BM 128
#define BN 128
#define BK 16
#define A_STRIDE 20    // floats; conflict-free a-frag LDS, 80B row = 16B aligned
#define B_STRIDE 136   // floats; conflict-free b-frag LDS, 544B row = 16B aligned

__device__ __forceinline__ void tf32_split(float f, uint32_t& hi, uint32_t& lo) {
    asm("cvt.rna.tf32.f32 %0, %1;" : "=r"(hi) : "f"(f));
    float d = f - __uint_as_float(hi);
    asm("cvt.rna.tf32.f32 %0, %1;" : "=r"(lo) : "f"(d));
}

#define MMA_TF32(c, a, b)                                                       \
    asm volatile(                                                               \
        "mma.sync.aligned.m16n8k8.row.col.f32.tf32.tf32.f32 "                   \
        "{%0,%1,%2,%3}, {%4,%5,%6,%7}, {%8,%9}, {%0,%1,%2,%3};"                 \
        : "+f"((c)[0]), "+f"((c)[1]), "+f"((c)[2]), "+f"((c)[3])                \
        : "r"((a)[0]), "r"((a)[1]), "r"((a)[2]), "r"((a)[3]),                   \
          "r"((b)[0]), "r"((b)[1]))

__device__ __forceinline__ void cp_async16(uint32_t smem, const void* gmem, int valid_bytes) {
    asm volatile("cp.async.cg.shared.global [%0], [%1], 16, %2;\n"
                 :: "r"(smem), "l"(gmem), "r"(valid_bytes));
}

template <int RELU>
__global__ void __launch_bounds__(256)
mma_gemm(const float* __restrict__ A, const float* __restrict__ B,
         const float* __restrict__ bias, float* __restrict__ C,
         int M, int N, int K) {
    __shared__ float As[2][BM][A_STRIDE];
    __shared__ float Bs[2][BK][B_STRIDE];

    const int tid = threadIdx.x;
    const int wid = tid >> 5;
    const int lane = tid & 31;
    const int warp_m = wid >> 2;        // 0..1  -> 64-row slab
    const int warp_n = wid & 3;         // 0..3  -> 32-col slab
    const int m0 = blockIdx.y * BM;
    const int n0 = blockIdx.x * BN;

    const uint32_t sA = (uint32_t)__cvta_generic_to_shared(&As[0][0][0]);
    const uint32_t sB = (uint32_t)__cvta_generic_to_shared(&Bs[0][0][0]);

    float acc[4][4][4];
#pragma unroll
    for (int i = 0; i < 4; i++)
#pragma unroll
        for (int j = 0; j < 4; j++)
#pragma unroll
            for (int k = 0; k < 4; k++) acc[i][j][k] = 0.f;

    const int KT = K / BK;

    auto load_stage = [&](int kt, int s) {
        const uint32_t baseA = sA + (uint32_t)s * (BM * A_STRIDE * 4);
        const uint32_t baseB = sB + (uint32_t)s * (BK * B_STRIDE * 4);
#pragma unroll
        for (int i = 0; i < 2; i++) {
            int f4 = tid + i * 256;                 // 0..511
            int row = f4 >> 2, c4 = f4 & 3;         // A tile: 128 rows x 4 f4/row
            const float* src = A + (size_t)(m0 + row) * K + kt * BK + c4 * 4;
            int v = (m0 + row < M) ? 16 : 0;
            cp_async16(baseA + (uint32_t)(row * A_STRIDE + c4 * 4) * 4, src, v);
        }
#pragma unroll
        for (int i = 0; i < 2; i++) {
            int f4 = tid + i * 256;
            int row = f4 >> 5, c4 = f4 & 31;        // B tile: 16 rows x 32 f4/row
            int col = c4 * 4;
            const float* src = B + (size_t)(kt * BK + row) * N + n0 + col;
            int v = (n0 + col < N) ? 16 : 0;
            cp_async16(baseB + (uint32_t)(row * B_STRIDE + col) * 4, src, v);
        }
    };

    load_stage(0, 0);
    asm volatile("cp.async.commit_group;\n");

    const int r4 = lane >> 2;       // 0..7
    const int c4l = lane & 3;       // 0..3

    for (int kt = 0; kt < KT; ++kt) {
        if (kt + 1 < KT) load_stage(kt + 1, (kt + 1) & 1);
        asm volatile("cp.async.commit_group;\n");
        asm volatile("cp.async.wait_group 1;\n");
        __syncthreads();

        const int s = kt & 1;
#pragma unroll
        for (int kk = 0; kk < BK; kk += 8) {
            uint32_t ah[4][4], al[4][4], bh[4][2], bl[4][2];
#pragma unroll
            for (int mi = 0; mi < 4; ++mi) {
                int rb = warp_m * 64 + mi * 16;
                float f0 = As[s][rb + r4][kk + c4l];
                float f1 = As[s][rb + r4 + 8][kk + c4l];
                float f2 = As[s][rb + r4][kk + c4l + 4];
                float f3 = As[s][rb + r4 + 8][kk + c4l + 4];
                tf32_split(f0, ah[mi][0], al[mi][0]);
                tf32_split(f1, ah[mi][1], al[mi][1]);
                tf32_split(f2, ah[mi][2], al[mi][2]);
                tf32_split(f3, ah[mi][3], al[mi][3]);
            }
#pragma unroll
            for (int ni = 0; ni < 4; ++ni) {
                int cb = warp_n * 32 + ni * 8 + r4;
                float f0 = Bs[s][kk + c4l][cb];
                float f1 = Bs[s][kk + c4l + 4][cb];
                tf32_split(f0, bh[ni][0], bl[ni][0]);
                tf32_split(f1, bh[ni][1], bl[ni][1]);
            }
#pragma unroll
            for (int mi = 0; mi < 4; ++mi)
#pragma unroll
                for (int ni = 0; ni < 4; ++ni) {
                    MMA_TF32(acc[mi][ni], ah[mi], bh[ni]);
                    MMA_TF32(acc[mi][ni], al[mi], bh[ni]);
                    MMA_TF32(acc[mi][ni], ah[mi], bl[ni]);
                }
        }
        __syncthreads();
    }

    const int cc2 = (lane & 3) * 2;
#pragma unroll
    for (int mi = 0; mi < 4; ++mi) {
        int row0 = m0 + warp_m * 64 + mi * 16 + r4;
        int row1 = row0 + 8;
#pragma unroll
        for (int ni = 0; ni < 4; ++ni) {
            int col = n0 + warp_n * 32 + ni * 8 + cc2;
            if (col >= N) continue;
            float b0 = bias ? bias[col] : 0.f;
            float b1 = bias ? bias[col + 1] : 0.f;
            if (row0 < M) {
                float v0 = acc[mi][ni][0] + b0;
                float v1 = acc[mi][ni][1] + b1;
                if (RELU) { v0 = fmaxf(v0, 0.f); v1 = fmaxf(v1, 0.f); }
                *(float2*)(C + (size_t)row0 * N + col) = make_float2(v0, v1);
            }
            if (row1 < M) {
                float v0 = acc[mi][ni][2] + b0;
                float v1 = acc[mi][ni][3] + b1;
                if (RELU) { v0 = fmaxf(v0, 0.f); v1 = fmaxf(v1, 0.f); }
                *(float2*)(C + (size_t)row1 * N + col) = make_float2(v0, v1);
            }
        }
    }
}

// ========== fused per-dst GATv2: logits + online softmax + aggregation ==========
// One 128-thread block per dst node. xl row loaded ONCE per edge and used for
// both the logit reduction and the weighted accumulation (online softmax).
__global__ void __launch_bounds__(128)
k_gat(const int* __restrict__ ei, const float* __restrict__ att,
      const float* __restrict__ bias, float* __restrict__ out,
      int HC, int C, int col_off) {
    const int i = blockIdx.x;
    const int tid = threadIdx.x;
    const int wid = tid >> 5;
    const int lane = tid & 31;
    const int start = g_row[i];
    const int end = g_row[i + 1];

    __shared__ float s_red[4][HEADS];     // per-warp partial logit sums
    __shared__ float s_m[HEADS], s_d[HEADS], s_scale[HEADS], s_p[HEADS];
    __shared__ float s_acc[512];

    // per-thread channels: c, c+128, c+256, c+384
    int   cja[4];
    int   hja[4];
    bool  vja[4];
    float xrv[4], atv[4];
    const float* xr_row = g_xr + (size_t)i * HC;
#pragma unroll
    for (int j = 0; j < 4; j++) {
        int c = tid + j * 128;
        bool v = c < HC;
        cja[j] = c;
        vja[j] = v;
        hja[j] = v ? (c / C) : 0;
        xrv[j] = v ? xr_row[c] : 0.f;
        atv[j] = v ? att[c] : 0.f;
    }
    if (tid < HEADS) { s_m[tid] = -1e30f; s_d[tid] = 0.f; }
    __syncthreads();

    float acc[4] = {0.f, 0.f, 0.f, 0.f};

    for (int t = start; t < end; ++t) {
        int e = g_eids[t];
        int src = (e < EE) ? ei[e] : (e - EE);
        const float* xl_row = g_xl + (size_t)src * HC;

        float xlv[4];
        float part[HEADS] = {0.f, 0.f, 0.f, 0.f};
#pragma unroll
        for (int j = 0; j < 4; j++) {
            if (vja[j]) {
                float x = xl_row[cja[j]];
                xlv[j] = x;
                float v = x + xrv[j];
                v = (v > 0.f) ? v : 0.2f * v;
                part[hja[j]] += v * atv[j];
            } else {
                xlv[j] = 0.f;
            }
        }
        // warp reduce 4 head-partials
#pragma unroll
        for (int off = 16; off; off >>= 1) {
#pragma unroll
            for (int h = 0; h < HEADS; h++)
                part[h] += __shfl_xor_sync(0xffffffffu, part[h], off);
        }
        if (lane == 0) {
#pragma unroll
            for (int h = 0; h < HEADS; h++) s_red[wid][h] = part[h];
        }
        __syncthreads();
        if (tid < HEADS) {
            float logit = s_red[0][tid] + s_red[1][tid] + s_red[2][tid] + s_red[3][tid];
            float m_old = s_m[tid];
            float m_new = fmaxf(m_old, logit);
            float scale = __expf(m_old - m_new);
            float p = __expf(logit - m_new);
            s_scale[tid] = scale;
            s_p[tid] = p;
            s_d[tid] = s_d[tid] * scale + p;
            s_m[tid] = m_new;
        }
        __syncthreads();
#pragma unroll
        for (int j = 0; j < 4; j++) {
            float sc = s_scale[hja[j]];
            float p = s_p[hja[j]];
            acc[j] = acc[j] * sc + p * xlv[j];
        }
        // next iteration's s_red write is ordered after this point by its own
        // pre-write __syncthreads (the one right after the warp reduce)
    }

    // normalize and write per-channel results to smem
#pragma unroll
    for (int j = 0; j < 4; j++) {
        if (vja[j]) s_acc[cja[j]] = acc[j] / s_d[hja[j]];
    }
    __syncthreads();

    // mean over heads + bias
    for (int cc = tid; cc < C; cc += 128) {
        float s = 0.f;
#pragma unroll
        for (int h = 0; h < HEADS; ++h) s += s_acc[h * C + cc];
        out[(size_t)i * OUTC + col_off + cc] = s * 0.25f + bias[cc];
    }
}

// ---------------- launcher ----------------
extern "C" void kernel_launch(void* const* d_in, const int* in_sizes, int n_in,
                              void* d_out, int out_size) {
    (void)in_sizes; (void)n_in; (void)out_size;
    const float* x    = (const float*)d_in[0];
    const float* fc_w = (const float*)d_in[1];
    const float* fc_b = (const float*)d_in[2];
    const int*   ei   = (const int*)d_in[19];
    float* out = (float*)d_out;

    float *hidden, *xl, *xr;
    cudaGetSymbolAddress((void**)&hidden, g_hidden);
    cudaGetSymbolAddress((void**)&xl, g_xl);
    cudaGetSymbolAddress((void**)&xr, g_xr);

    // CSR build (scatter after the fc GEMM so the ncu window lands on the GEMM)
    k_zero_cnt<<<(NN + 255) / 256, 256>>>();
    k_hist<<<(EP + 255) / 256, 256>>>(ei);
    k_scan<<<1, 1024>>>();

    // hidden = relu(x @ fc_w + fc_b)
    dim3 g1((DH + 127) / 128, (NN + 127) / 128);
    mma_gemm<1><<<g1, 256>>>(x, fc_w, fc_b, hidden, NN, DH, DIN);

    k_scatter<<<(EP + 255) / 256, 256>>>(ei);

    struct Conv { int wl, wr, att, b, C; size_t out_base; int col; };
    const Conv convs[4] = {
        { 3,  4,  5,  6, 128, 0,                  0   },   // mu
        { 7,  8,  9, 10, 128, (size_t)NN * OUTC,  0   },   // logstd
        {11, 12, 13, 14, 100, 0,                  128 },   // addon mu
        {15, 16, 17, 18, 100, (size_t)NN * OUTC,  128 },   // addon logstd
    };

    for (int cv = 0; cv < 4; ++cv) {
        const Conv c = convs[cv];
        int HC = HEADS * c.C;
        dim3 gg((HC + 127) / 128, (NN + 127) / 128);
        mma_gemm<0><<<gg, 256>>>(hidden, (const float*)d_in[c.wl], nullptr, xl, NN, HC, DH);
        mma_gemm<0><<<gg, 256>>>(hidden, (const float*)d_in[c.wr], nullptr, xr, NN, HC, DH);
        k_gat<<<NN, 128>>>(ei, (const float*)d_in[c.att], (const float*)d_in[c.b],
                           out + c.out_base, HC, c.C, c.col);
    }
}